// round 9
// baseline (speedup 1.0000x reference)
#include <cuda_runtime.h>

#define BB 64
#define EE 8978
#define E2C 4489
#define PAIRS 2245            // ceil(E2C/2)
#define N1 (BB*EE)            // 574592
#define N2 (BB*E2C)           // 287296
#define SLOPE 0.33f
#define EPSBN 1e-5f

// ---------------- device scratch ----------------
__device__ float g_out32[9193472];   // pooled pre-BN (N2*32); later layer1 pre-BN out
__device__ float g_xp  [9193472];    // act0 output = layer1 T0
__device__ float g_Ta  [9193472];    // layer1 T1
__device__ float g_Tb  [9193472];    // layer1 T2
__device__ float g_z[N2];
__device__ float g_H1[64*256];
__device__ float g_H2[64*128];
__device__ double g_acc0[64];
__device__ double g_acc1[64];
__device__ double g_acc2[2];
__device__ float g_scale0[32], g_shift0[32];

// ---------------- init ----------------
__global__ void kZero() {
    int t = threadIdx.x;
    if (t < 64) g_acc0[t] = 0.0;
    else if (t < 128) g_acc1[t - 64] = 0.0;
    else if (t < 130) g_acc2[t - 128] = 0.0;
}

// ---------------- fused layer0: block per graph, fields in smem ----------------
__global__ void kL0(const float* __restrict__ x, const int* __restrict__ src,
                    const float* __restrict__ ew, const float* __restrict__ W0,
                    const float* __restrict__ b0) {
    extern __shared__ float sm[];
    float* xs  = sm;
    float* t1s = sm + EE;
    float* t2s = sm + 2 * EE;
    __shared__ float s_sum[32], s_sq[32];

    int g = blockIdx.x;
    int tid = threadIdx.x;
    int lane = tid & 31, warp = tid >> 5;      // 32 warps of 1024 threads
    int nbase = g * EE;
    int ebase = nbase * 16;

    for (int i = tid; i < EE; i += 1024) xs[i] = x[nbase + i];
    if (tid < 32) { s_sum[tid] = 0.f; s_sq[tid] = 0.f; }
    __syncthreads();

    // step1: T1 = x - L x
    for (int p = warp; p < E2C; p += 32) {
        int e = ebase + p * 32 + lane;
        int ls = src[e] - nbase;
        float a = ew[e] * xs[ls];
        a += __shfl_xor_sync(~0u, a, 8);
        a += __shfl_xor_sync(~0u, a, 4);
        a += __shfl_xor_sync(~0u, a, 2);
        a += __shfl_xor_sync(~0u, a, 1);
        if (lane == 0)  t1s[2 * p]     = xs[2 * p]     - a;
        if (lane == 16) t1s[2 * p + 1] = xs[2 * p + 1] - a;
    }
    __syncthreads();

    // step2: T2 = (3 T1 - L T1 - x) / 2
    for (int p = warp; p < E2C; p += 32) {
        int e = ebase + p * 32 + lane;
        int ls = src[e] - nbase;
        float a = ew[e] * t1s[ls];
        a += __shfl_xor_sync(~0u, a, 8);
        a += __shfl_xor_sync(~0u, a, 4);
        a += __shfl_xor_sync(~0u, a, 2);
        a += __shfl_xor_sync(~0u, a, 1);
        if (lane == 0)  t2s[2 * p]     = 0.5f * (3.f * t1s[2 * p]     - a - xs[2 * p]);
        if (lane == 16) t2s[2 * p + 1] = 0.5f * (3.f * t1s[2 * p + 1] - a - xs[2 * p + 1]);
    }
    __syncthreads();

    // step3: T3 = (5 T2 - L T2 - 2 T1)/3 ; project to 32 ch; pre-BN max pool
    float w0 = W0[lane], w1 = W0[32 + lane], w2 = W0[64 + lane], w3 = W0[96 + lane];
    float bb = b0[lane];
    float lsum = 0.f, lsq = 0.f;
    for (int p = warp; p < E2C; p += 32) {
        int e = ebase + p * 32 + lane;
        int ls = src[e] - nbase;
        float a = ew[e] * t2s[ls];
        a += __shfl_xor_sync(~0u, a, 8);
        a += __shfl_xor_sync(~0u, a, 4);
        a += __shfl_xor_sync(~0u, a, 2);
        a += __shfl_xor_sync(~0u, a, 1);
        float t3 = 0.f;
        if ((lane & 15) == 0) {
            int n = 2 * p + (lane >> 4);
            t3 = (5.f * t2s[n] - a - 2.f * t1s[n]) * (1.f / 3.f);
        }
        float t3a = __shfl_sync(~0u, t3, 0);
        float t3b = __shfl_sync(~0u, t3, 16);
        float xa  = xs[2 * p],  xb  = xs[2 * p + 1];
        float ta1 = t1s[2 * p], tb1 = t1s[2 * p + 1];
        float ta2 = t2s[2 * p], tb2 = t2s[2 * p + 1];
        float oa = fmaf(xa, w0, fmaf(ta1, w1, fmaf(ta2, w2, fmaf(t3a, w3, bb))));
        float ob = fmaf(xb, w0, fmaf(tb1, w1, fmaf(tb2, w2, fmaf(t3b, w3, bb))));
        lsum += oa + ob;
        lsq  += oa * oa + ob * ob;
        g_out32[((size_t)(g * E2C + p)) * 32 + lane] = fmaxf(oa, ob);
    }
    atomicAdd(&s_sum[lane], lsum);
    atomicAdd(&s_sq[lane], lsq);
    __syncthreads();
    if (tid < 32) {
        atomicAdd(&g_acc0[tid],      (double)s_sum[tid]);
        atomicAdd(&g_acc0[32 + tid], (double)s_sq[tid]);
    }
}

// ---------------- BN0 finalize ----------------
__global__ void kBNfin0(const float* __restrict__ g, const float* __restrict__ be) {
    int c = threadIdx.x;
    double mean = g_acc0[c] / (double)N1;
    double var  = g_acc0[32 + c] / (double)N1 - mean * mean;
    float scl = g[c] * rsqrtf((float)var + EPSBN);
    g_scale0[c] = scl;
    g_shift0[c] = be[c] - (float)mean * scl;
}

// ---------------- layer1 step1: act0 (BN0+leaky) on the fly + matvec ----------
// writes g_xp = act(own), g_Ta = T1 = act - L act
__global__ void kMV1A(const int* __restrict__ src, const float* __restrict__ ew) {
    int warp = (blockIdx.x * blockDim.x + threadIdx.x) >> 5;   // = node
    int lane = threadIdx.x & 31;
    float sc = g_scale0[lane], sh = g_shift0[lane];
    int e = warp * 16 + (lane & 15);
    int s = src[e];
    float wv = ew[e];
    float acc = 0.f;
#pragma unroll
    for (int j = 0; j < 16; j++) {
        int   sj = __shfl_sync(0xffffffffu, s,  j);
        float wj = __shfl_sync(0xffffffffu, wv, j);
        float v = g_out32[sj * 32 + lane] * sc + sh;
        v = v > 0.f ? v : SLOPE * v;
        acc += wj * v;
    }
    float own = g_out32[warp * 32 + lane] * sc + sh;
    own = own > 0.f ? own : SLOPE * own;
    g_xp[warp * 32 + lane] = own;
    g_Ta[warp * 32 + lane] = own - acc;
}

// ---------------- layer1 step2: T2 = 1.5 T1 - 0.5 L T1 - 0.5 T0 ---------------
__global__ void kMV2(const int* __restrict__ src, const float* __restrict__ ew) {
    int warp = (blockIdx.x * blockDim.x + threadIdx.x) >> 5;
    int lane = threadIdx.x & 31;
    int e = warp * 16 + (lane & 15);
    int s = src[e];
    float wv = ew[e];
    float acc = 0.f;
#pragma unroll
    for (int j = 0; j < 16; j++) {
        int   sj = __shfl_sync(0xffffffffu, s,  j);
        float wj = __shfl_sync(0xffffffffu, wv, j);
        acc += wj * g_Ta[sj * 32 + lane];
    }
    float o = 1.5f * g_Ta[warp * 32 + lane] - 0.5f * acc - 0.5f * g_xp[warp * 32 + lane];
    g_Tb[warp * 32 + lane] = o;
}

// ---------------- layer1 step3 + output GEMM + BN1 stats ----------------------
// block = 256 threads, 64 nodes. T3 computed straight into smem; GEMM over
// smem-resident T0..T3 tiles; pre-BN out to g_out32.
__global__ void kMV3G(const int* __restrict__ src, const float* __restrict__ ew,
                      const float* __restrict__ W1, const float* __restrict__ b1) {
    __shared__ float Wsh[128 * 32];
    __shared__ float T0s[64 * 32], T1s[64 * 32], T2s[64 * 32], T3s[64 * 32];
    __shared__ float ssum[32], ssq[32];
    int tid = threadIdx.x, c = tid & 31, rg = tid >> 5;
    for (int i = tid; i < 4096; i += 256) Wsh[i] = W1[i];
    if (tid < 32) { ssum[tid] = 0.f; ssq[tid] = 0.f; }
    int n0 = blockIdx.x * 64;
#pragma unroll
    for (int q = 0; q < 8; q++) {
        int row = rg + 8 * q;
        T0s[row * 32 + c] = g_xp[(n0 + row) * 32 + c];
        T1s[row * 32 + c] = g_Ta[(n0 + row) * 32 + c];
        T2s[row * 32 + c] = g_Tb[(n0 + row) * 32 + c];
    }
    __syncthreads();
    // gather phase: warp per node, 8 passes
#pragma unroll
    for (int it = 0; it < 8; it++) {
        int local = it * 8 + rg;
        int node = n0 + local;
        int e = node * 16 + (c & 15);
        int s = src[e];
        float wv = ew[e];
        float acc = 0.f;
#pragma unroll
        for (int j = 0; j < 16; j++) {
            int   sj = __shfl_sync(0xffffffffu, s,  j);
            float wj = __shfl_sync(0xffffffffu, wv, j);
            acc += wj * g_Tb[sj * 32 + c];
        }
        T3s[local * 32 + c] =
            (5.f * T2s[local * 32 + c] - acc - 2.f * T1s[local * 32 + c]) * (1.f / 3.f);
    }
    __syncthreads();
    // GEMM phase
    float acc[8];
#pragma unroll
    for (int q = 0; q < 8; q++) acc[q] = 0.f;
    const float* Tarr[4] = { T0s, T1s, T2s, T3s };
#pragma unroll
    for (int k = 0; k < 4; k++) {
        const float* Ts = Tarr[k];
#pragma unroll
        for (int i = 0; i < 32; i += 4) {
            float wa = Wsh[(k * 32 + i) * 32 + c];
            float wb = Wsh[(k * 32 + i + 1) * 32 + c];
            float wc = Wsh[(k * 32 + i + 2) * 32 + c];
            float wd = Wsh[(k * 32 + i + 3) * 32 + c];
#pragma unroll
            for (int q = 0; q < 8; q++) {
                float4 t = *(const float4*)&Ts[(rg + 8 * q) * 32 + i];
                acc[q] += t.x * wa + t.y * wb + t.z * wc + t.w * wd;
            }
        }
    }
    float bv = b1[c];
    float lsum = 0.f, lsq = 0.f;
#pragma unroll
    for (int q = 0; q < 8; q++) {
        float o = acc[q] + bv;
        g_out32[(n0 + rg + 8 * q) * 32 + c] = o;
        lsum += o; lsq += o * o;
    }
    atomicAdd(&ssum[c], lsum);
    atomicAdd(&ssq[c], lsq);
    __syncthreads();
    if (tid < 32) {
        atomicAdd(&g_acc1[tid], (double)lsum * 0.0 + (double)ssum[tid]);
        atomicAdd(&g_acc1[32 + tid], (double)ssq[tid]);
    }
}

// ---------------- fused layer2: block per graph, all in smem ------------------
// BN1 finalize (from g_acc1) + LeakyReLU + W2 projection to 4 scalar fields,
// then dead-channel-pruned Laguerre recurrence:
//   z = Y0 + U1[1] + U2[2] + U3[3] + b2 ; BN2 stats accumulated.
__global__ void kL2(const int* __restrict__ src, const float* __restrict__ ew,
                    const float* __restrict__ W2, const float* __restrict__ b2,
                    const float* __restrict__ g1, const float* __restrict__ be1) {
    extern __shared__ float sm[];
    float* Y0 = sm;
    float* Y1 = sm + E2C;
    float* Y2 = sm + 2 * E2C;
    float* Y3 = sm + 3 * E2C;
    float* A1 = sm + 4 * E2C;   // U1 ch1..3
    float* A2 = sm + 5 * E2C;
    float* A3 = sm + 6 * E2C;
    float* B2 = sm + 7 * E2C;   // U2 ch2..3
    float* B3 = sm + 8 * E2C;
    __shared__ float s_bs[2];

    int g = blockIdx.x;
    int tid = threadIdx.x;
    int lane = tid & 31, warp = tid >> 5;   // 32 warps
    int nbase = g * E2C;
    int ebase = nbase * 16;

    // BN1 scale for this lane (=channel), computed redundantly per thread
    float sc1, sh1;
    {
        double mean = g_acc1[lane] / (double)N2;
        double var  = g_acc1[32 + lane] / (double)N2 - mean * mean;
        sc1 = g1[lane] * rsqrtf((float)var + EPSBN);
        sh1 = be1[lane] - (float)mean * sc1;
    }
    if (tid < 2) s_bs[tid] = 0.f;

    // projection: warp per node
    float w2_0 = W2[lane], w2_1 = W2[32 + lane], w2_2 = W2[64 + lane], w2_3 = W2[96 + lane];
    for (int n = warp; n < E2C; n += 32) {
        float v = g_out32[(nbase + n) * 32 + lane] * sc1 + sh1;
        v = v > 0.f ? v : SLOPE * v;
        float p0 = v * w2_0, p1 = v * w2_1, p2 = v * w2_2, p3 = v * w2_3;
#pragma unroll
        for (int off = 16; off; off >>= 1) {
            p0 += __shfl_xor_sync(~0u, p0, off);
            p1 += __shfl_xor_sync(~0u, p1, off);
            p2 += __shfl_xor_sync(~0u, p2, off);
            p3 += __shfl_xor_sync(~0u, p3, off);
        }
        if (lane == 0) { Y0[n] = p0; Y1[n] = p1; Y2[n] = p2; Y3[n] = p3; }
    }
    __syncthreads();

    // step1: U1_ch = Y_ch - L Y_ch  for ch in {1,2,3}
    for (int p = warp; p < PAIRS; p += 32) {
        int n0 = 2 * p;
        bool hasB = (n0 + 1 < E2C);
        bool valid = (lane < 16) || hasB;
        int e = ebase + n0 * 16 + lane;
        float w = 0.f; int ls = 0;
        if (valid) { w = ew[e]; ls = src[e] - nbase; }
        float a1 = w * Y1[ls], a2 = w * Y2[ls], a3 = w * Y3[ls];
#pragma unroll
        for (int off = 8; off; off >>= 1) {
            a1 += __shfl_xor_sync(~0u, a1, off);
            a2 += __shfl_xor_sync(~0u, a2, off);
            a3 += __shfl_xor_sync(~0u, a3, off);
        }
        if (lane == 0) {
            A1[n0] = Y1[n0] - a1; A2[n0] = Y2[n0] - a2; A3[n0] = Y3[n0] - a3;
        }
        if (lane == 16 && hasB) {
            A1[n0+1] = Y1[n0+1] - a1; A2[n0+1] = Y2[n0+1] - a2; A3[n0+1] = Y3[n0+1] - a3;
        }
    }
    __syncthreads();

    // step2: U2_ch = (3 U1_ch - L U1_ch - Y_ch)/2  for ch in {2,3}
    for (int p = warp; p < PAIRS; p += 32) {
        int n0 = 2 * p;
        bool hasB = (n0 + 1 < E2C);
        bool valid = (lane < 16) || hasB;
        int e = ebase + n0 * 16 + lane;
        float w = 0.f; int ls = 0;
        if (valid) { w = ew[e]; ls = src[e] - nbase; }
        float a2 = w * A2[ls], a3 = w * A3[ls];
#pragma unroll
        for (int off = 8; off; off >>= 1) {
            a2 += __shfl_xor_sync(~0u, a2, off);
            a3 += __shfl_xor_sync(~0u, a3, off);
        }
        if (lane == 0) {
            B2[n0] = 0.5f * (3.f * A2[n0] - a2 - Y2[n0]);
            B3[n0] = 0.5f * (3.f * A3[n0] - a3 - Y3[n0]);
        }
        if (lane == 16 && hasB) {
            B2[n0+1] = 0.5f * (3.f * A2[n0+1] - a2 - Y2[n0+1]);
            B3[n0+1] = 0.5f * (3.f * A3[n0+1] - a3 - Y3[n0+1]);
        }
    }
    __syncthreads();

    // step3: u3 = (5 B3 - L B3 - 2 A3)/3 ; z = Y0 + A1 + B2 + u3 + b2 ; stats
    float bv = b2[0];
    float lsum = 0.f, lsq = 0.f;
    for (int p = warp; p < PAIRS; p += 32) {
        int n0 = 2 * p;
        bool hasB = (n0 + 1 < E2C);
        bool valid = (lane < 16) || hasB;
        int e = ebase + n0 * 16 + lane;
        float w = 0.f; int ls = 0;
        if (valid) { w = ew[e]; ls = src[e] - nbase; }
        float a3 = w * B3[ls];
#pragma unroll
        for (int off = 8; off; off >>= 1)
            a3 += __shfl_xor_sync(~0u, a3, off);
        if (lane == 0) {
            float u3 = (5.f * B3[n0] - a3 - 2.f * A3[n0]) * (1.f / 3.f);
            float z = Y0[n0] + A1[n0] + B2[n0] + u3 + bv;
            g_z[nbase + n0] = z;
            lsum += z; lsq += z * z;
        }
        if (lane == 16 && hasB) {
            float u3 = (5.f * B3[n0+1] - a3 - 2.f * A3[n0+1]) * (1.f / 3.f);
            float z = Y0[n0+1] + A1[n0+1] + B2[n0+1] + u3 + bv;
            g_z[nbase + n0 + 1] = z;
            lsum += z; lsq += z * z;
        }
    }
    if ((lane & 15) == 0) {
        atomicAdd(&s_bs[0], lsum);
        atomicAdd(&s_bs[1], lsq);
    }
    __syncthreads();
    if (tid == 0) {
        atomicAdd(&g_acc2[0], (double)s_bs[0]);
        atomicAdd(&g_acc2[1], (double)s_bs[1]);
    }
}

// ---------------- MLP head ----------------
// D1 folds BN2 finalize (from g_acc2) + leaky + lin1
__global__ void kD1(const float* __restrict__ lin1W, const float* __restrict__ lin1b,
                    const float* __restrict__ g2, const float* __restrict__ be2) {
    __shared__ float As[16][64];
    __shared__ float Ws[64][8];
    int tid = threadIdx.x;
    int c = tid & 7, r = tid >> 3;
    int c0 = (blockIdx.x & 31) * 8;
    int r0 = (blockIdx.x >> 5) * 16;
    float scale, shift;
    {
        double mean = g_acc2[0] / (double)N2;
        double var  = g_acc2[1] / (double)N2 - mean * mean;
        scale = g2[0] * rsqrtf((float)var + EPSBN);
        shift = be2[0] - (float)mean * scale;
    }
    float acc = 0.f;
    for (int e0 = 0; e0 < E2C; e0 += 64) {
        __syncthreads();
        for (int t = tid; t < 1024; t += 128) {
            int rr = t >> 6, ii = t & 63, e = e0 + ii;
            float v = 0.f;
            if (e < E2C) {
                float z = g_z[(r0 + rr) * E2C + e] * scale + shift;
                v = z > 0.f ? z : SLOPE * z;
            }
            As[rr][ii] = v;
        }
        for (int t = tid; t < 512; t += 128) {
            int ii = t >> 3, cc = t & 7, e = e0 + ii;
            Ws[ii][cc] = (e < E2C) ? lin1W[e * 256 + c0 + cc] : 0.f;
        }
        __syncthreads();
#pragma unroll 8
        for (int i = 0; i < 64; i++) acc += As[r][i] * Ws[i][c];
    }
    g_H1[(r0 + r) * 256 + c0 + c] = acc + lin1b[c0 + c];
}

__global__ void kD2(const float* __restrict__ bn1g, const float* __restrict__ bn1b,
                    const float* __restrict__ lin2W, const float* __restrict__ lin2b) {
    __shared__ float sc[256], sh[256], As[2][256];
    int tid = threadIdx.x;
    {
        int col = tid;
        float s = 0.f, q = 0.f;
        for (int r = 0; r < 64; r++) { float v = g_H1[r * 256 + col]; s += v; q += v * v; }
        float mean = s * (1.f / 64.f);
        float var  = q * (1.f / 64.f) - mean * mean;
        float scl = bn1g[col] * rsqrtf(var + EPSBN);
        sc[col] = scl; sh[col] = bn1b[col] - mean * scl;
    }
    __syncthreads();
    int r0 = blockIdx.x * 2;
    for (int t = tid; t < 512; t += 256) {
        int rr = t >> 8, k = t & 255;
        float v = g_H1[(r0 + rr) * 256 + k] * sc[k] + sh[k];
        As[rr][k] = v > 0.f ? v : 0.f;
    }
    __syncthreads();
    int c = tid & 127, rr = tid >> 7;
    float acc = lin2b[c];
#pragma unroll 8
    for (int k = 0; k < 256; k++) acc += As[rr][k] * lin2W[k * 128 + c];
    g_H2[(r0 + rr) * 128 + c] = acc;
}

__global__ void kD3(const float* __restrict__ bn2g, const float* __restrict__ bn2b,
                    const float* __restrict__ lin3W, const float* __restrict__ lin3b,
                    float* __restrict__ out) {
    __shared__ float sc[128], sh[128];
    int tid = threadIdx.x;
    if (tid < 128) {
        float s = 0.f, q = 0.f;
        for (int r = 0; r < 64; r++) { float v = g_H2[r * 128 + tid]; s += v; q += v * v; }
        float mean = s * (1.f / 64.f);
        float var  = q * (1.f / 64.f) - mean * mean;
        float scl = bn2g[tid] * rsqrtf(var + EPSBN);
        sc[tid] = scl; sh[tid] = bn2b[tid] - mean * scl;
    }
    __syncthreads();
    int lane = tid & 31, w = tid >> 5;
    for (int r = w; r < 64; r += 8) {
        float acc = 0.f;
        for (int kk = lane; kk < 128; kk += 32) {
            float v = g_H2[r * 128 + kk] * sc[kk] + sh[kk];
            v = v > 0.f ? v : 0.f;
            acc += v * lin3W[kk];
        }
#pragma unroll
        for (int off = 16; off; off >>= 1)
            acc += __shfl_xor_sync(0xffffffffu, acc, off);
        if (lane == 0) out[r] = acc + lin3b[0];
    }
}

// ---------------- host launcher ----------------
extern "C" void kernel_launch(void* const* d_in, const int* in_sizes, int n_in,
                              void* d_out, int out_size) {
    const float* x    = (const float*)d_in[0];
    const int*   src1 = (const int*)  d_in[1];
    const float* ew1  = (const float*)d_in[2];
    const int*   src2 = (const int*)  d_in[3];
    const float* ew2  = (const float*)d_in[4];
    const float* W0 = (const float*)d_in[5];
    const float* b0 = (const float*)d_in[6];
    const float* g0 = (const float*)d_in[7];
    const float* be0= (const float*)d_in[8];
    const float* W1 = (const float*)d_in[9];
    const float* b1 = (const float*)d_in[10];
    const float* g1 = (const float*)d_in[11];
    const float* be1= (const float*)d_in[12];
    const float* W2 = (const float*)d_in[13];
    const float* b2 = (const float*)d_in[14];
    const float* g2 = (const float*)d_in[15];
    const float* be2= (const float*)d_in[16];
    const float* lin1W = (const float*)d_in[17];
    const float* lin1b = (const float*)d_in[18];
    const float* bn1g  = (const float*)d_in[19];
    const float* bn1b  = (const float*)d_in[20];
    const float* lin2W = (const float*)d_in[21];
    const float* lin2b = (const float*)d_in[22];
    const float* bn2g  = (const float*)d_in[23];
    const float* bn2b  = (const float*)d_in[24];
    const float* lin3W = (const float*)d_in[25];
    const float* lin3b = (const float*)d_in[26];
    float* out = (float*)d_out;

    const int kL0smem = 3 * EE * (int)sizeof(float);     // 107,736 B
    const int kL2smem = 9 * E2C * (int)sizeof(float);    // 161,604 B
    cudaFuncSetAttribute(kL0, cudaFuncAttributeMaxDynamicSharedMemorySize, kL0smem);
    cudaFuncSetAttribute(kL2, cudaFuncAttributeMaxDynamicSharedMemorySize, kL2smem);

    kZero<<<1, 256>>>();

    // ---- layer0 fused ----
    kL0<<<BB, 1024, kL0smem>>>(x, src1, ew1, W0, b0);
    kBNfin0<<<1, 32>>>(g0, be0);

    // ---- layer1 ----
    kMV1A<<<N2 / 8, 256>>>(src2, ew2);
    kMV2<<<N2 / 8, 256>>>(src2, ew2);
    kMV3G<<<N2 / 64, 256>>>(src2, ew2, W1, b1);

    // ---- layer2 fused (BN1 + act + proj + pruned recurrence + z + BN2 stats) ----
    kL2<<<BB, 1024, kL2smem>>>(src2, ew2, W2, b2, g1, be1);

    // ---- MLP head (BN2 finalize folded into kD1) ----
    kD1<<<128, 128>>>(lin1W, lin1b, g2, be2);
    kD2<<<32, 256>>>(bn1g, bn1b, lin2W, lin2b);
    kD3<<<1, 256>>>(bn2g, bn2b, lin3W, lin3b, out);
}